// round 5
// baseline (speedup 1.0000x reference)
#include <cuda_runtime.h>
#include <cuda_bf16.h>
#include <math.h>

// Problem constants
#define BB 4
#define SS 2048
#define EE 128
#define HH 4
#define HD 32
#define NTOK (BB*SS)          // 8192
#define NBH  (BB*HH)          // 16

// Scratch (device globals: allocation-free rule)
__device__ float        g_X[NTOK*512];
__device__ float        g_Q256[NTOK*256];
__device__ float        g_H[NTOK*256];
__device__ unsigned int g_qb[NBH*SS*16];    // q bf16x2 [B*H,S,16]
__device__ unsigned int g_kb[NBH*SS*16];    // k bf16x2
__device__ float        g_v[NBH*SS*HD];     // v f32 [B*H,S,32]
__device__ float        g_o[NBH*SS*HD];     // attention output
__device__ float        g_base[(size_t)BB*SS*SS];

// ---------------------------------------------------------------------------
__device__ __forceinline__ unsigned int f2tf32(float x) {
    unsigned int r;
    asm("cvt.rna.tf32.f32 %0, %1;" : "=r"(r) : "f"(x));
    return r;
}

// ---------------------------------------------------------------------------
// Kernel 1: build X512 and Q256 from embedding gathers
// ---------------------------------------------------------------------------
__global__ void build_kernel(const int* __restrict__ item_in,
                             const int* __restrict__ skill_in,
                             const int* __restrict__ label_in,
                             const int* __restrict__ item_ids,
                             const int* __restrict__ skill_ids,
                             const float* __restrict__ item_emb,
                             const float* __restrict__ skill_emb)
{
    int t = blockIdx.x;
    int d = threadIdx.x; // 0..127
    int lb = label_in[t];
    float itv = item_emb[(size_t)item_in[t]*EE + d];
    float skv = skill_emb[(size_t)skill_in[t]*EE + d];
    float* x = g_X + (size_t)t*512;
    x[d]       = lb ? itv : 0.f;
    x[128 + d] = lb ? 0.f : itv;
    x[256 + d] = lb ? skv : 0.f;
    x[384 + d] = lb ? 0.f : skv;
    float* qx = g_Q256 + (size_t)t*256;
    qx[d]       = item_emb[(size_t)item_ids[t]*EE + d];
    qx[128 + d] = skill_emb[(size_t)skill_ids[t]*EE + d];
}

// ---------------------------------------------------------------------------
// Kernel 2: precompute base = c_t*time_attn + c_r*rel_attn  (head-invariant)
// ---------------------------------------------------------------------------
__global__ __launch_bounds__(256) void base_kernel(const float* __restrict__ ts,
                                                   const float* __restrict__ rel,
                                                   const float* __restrict__ l1p,
                                                   const float* __restrict__ l2p)
{
    __shared__ float et[SS];
    __shared__ float er[SS];
    __shared__ float red[32];

    const int tid = threadIdx.x;
    const int row = blockIdx.x;
    const int q = row & (SS-1);
    const float l1 = *l1p, l2 = *l2p;

    const float* tsrow  = ts  + (size_t)row*SS;
    const float* relrow = rel + (size_t)row*SS;

    float st = 0.f, mr = -1e30f;
    #pragma unroll
    for (int j = 0; j < 8; j++) {
        int k = tid + 256*j;
        float tv = tsrow[k];
        float e1 = (k <= q) ? __expf(__expf(-fabsf(tv))) : 0.f;
        et[k] = e1; st += e1;
        float rv = relrow[k];
        float rr = (k > q && rv != 0.f) ? rv : -10000.f;
        er[k] = rr; mr = fmaxf(mr, rr);
    }
    #pragma unroll
    for (int o = 16; o; o >>= 1) {
        st += __shfl_xor_sync(0xffffffffu, st, o);
        mr  = fmaxf(mr, __shfl_xor_sync(0xffffffffu, mr, o));
    }
    if ((tid & 31) == 0) { red[tid>>5] = st; red[8 + (tid>>5)] = mr; }
    __syncthreads();
    if (tid == 0) {
        float s = 0.f, m = -1e30f;
        #pragma unroll
        for (int i = 0; i < 8; i++) { s += red[i]; m = fmaxf(m, red[8+i]); }
        red[16] = s; red[17] = m;
    }
    __syncthreads();
    st = red[16]; mr = red[17];

    float sr = 0.f;
    #pragma unroll
    for (int j = 0; j < 8; j++) {
        int k = tid + 256*j;
        float e = __expf(er[k] - mr);
        er[k] = e; sr += e;
    }
    #pragma unroll
    for (int o = 16; o; o >>= 1) sr += __shfl_xor_sync(0xffffffffu, sr, o);
    if ((tid & 31) == 0) red[tid>>5] = sr;
    __syncthreads();
    if (tid == 0) {
        float s = 0.f;
        #pragma unroll
        for (int i = 0; i < 8; i++) s += red[i];
        red[18] = s;
    }
    __syncthreads();
    sr = red[18];

    const float ct = (1.f - l1) * l2 / st;
    const float cr = l1 / sr;
    float* brow = g_base + (size_t)row*SS;
    #pragma unroll
    for (int j = 0; j < 8; j++) {
        int k = tid + 256*j;
        brow[k] = fmaf(ct, et[k], cr * er[k]);
    }
}

// ---------------------------------------------------------------------------
// Kernel 3: tiled SGEMM with z-dispatch over up to 3 weight sets.
// ---------------------------------------------------------------------------
__global__ __launch_bounds__(256) void sgemm_kernel(
    const float* __restrict__ W0, const float* __restrict__ B0,
    const float* __restrict__ W1, const float* __restrict__ B1,
    const float* __restrict__ W2, const float* __restrict__ B2,
    int K, int N, int obase)
{
    __shared__ float As[16*68];
    __shared__ float Ws[16*64];

    const int z = blockIdx.z;
    const float* W    = (z == 0) ? W0 : (z == 1) ? W1 : W2;
    const float* bias = (z == 0) ? B0 : (z == 1) ? B1 : B2;
    const int osel = obase + z;
    const float* A = (osel == 0) ? g_X : (osel == 1) ? g_Q256 : g_H;

    int tid = threadIdx.x;
    int bx = blockIdx.x, by = blockIdx.y;
    int tx = tid & 15, ty = tid >> 4;

    float acc[4][4];
    #pragma unroll
    for (int i = 0; i < 4; i++)
        #pragma unroll
        for (int j = 0; j < 4; j++) acc[i][j] = 0.f;

    int arow  = tid >> 2;
    int acol4 = (tid & 3) * 4;
    int wrow  = tid >> 4;
    int wcol4 = (tid & 15) * 4;

    const float* Aptr = A + ((size_t)(by*64 + arow))*K + acol4;
    const float* Wptr = W + (size_t)wrow*N + bx*64 + wcol4;

    for (int kk = 0; kk < K; kk += 16) {
        float4 av = *(const float4*)(Aptr + kk);
        float4 wv = *(const float4*)(Wptr + (size_t)kk*N);
        __syncthreads();
        As[(acol4+0)*68 + arow] = av.x;
        As[(acol4+1)*68 + arow] = av.y;
        As[(acol4+2)*68 + arow] = av.z;
        As[(acol4+3)*68 + arow] = av.w;
        *(float4*)&Ws[wrow*64 + wcol4] = wv;
        __syncthreads();
        #pragma unroll
        for (int k = 0; k < 16; k++) {
            float4 a = *(const float4*)&As[k*68 + ty*4];
            float4 bq = *(const float4*)&Ws[k*64 + tx*4];
            float ar[4] = {a.x, a.y, a.z, a.w};
            float br[4] = {bq.x, bq.y, bq.z, bq.w};
            #pragma unroll
            for (int i = 0; i < 4; i++)
                #pragma unroll
                for (int j = 0; j < 4; j++)
                    acc[i][j] += ar[i] * br[j];
        }
    }

    int m0 = by*64 + ty*4, n0 = bx*64 + tx*4;
    if (osel == 0) {
        #pragma unroll
        for (int i = 0; i < 4; i++)
            #pragma unroll
            for (int j = 0; j < 4; j++)
                g_H[(size_t)(m0+i)*256 + n0 + j] = fmaxf(acc[i][j] + bias[n0+j], 0.f);
    } else if (osel == 3) {
        #pragma unroll
        for (int i = 0; i < 4; i++) {
            int m = m0 + i, bb = m >> 11, s = m & (SS-1);
            int h = n0 >> 5, hd = n0 & 31;
            float* o = g_v + (((size_t)(bb*HH + h))*SS + s)*HD + hd;
            #pragma unroll
            for (int j = 0; j < 4; j++) o[j] = acc[i][j] + bias[n0+j];
        }
    } else {
        unsigned int* dstbase = (osel == 1) ? g_qb : g_kb;
        #pragma unroll
        for (int i = 0; i < 4; i++) {
            int m = m0 + i, bb = m >> 11, s = m & (SS-1);
            int h = n0 >> 5, hd = n0 & 31;
            float v0 = acc[i][0] + bias[n0+0];
            float v1 = acc[i][1] + bias[n0+1];
            float v2 = acc[i][2] + bias[n0+2];
            float v3 = acc[i][3] + bias[n0+3];
            __nv_bfloat162 p0 = __floats2bfloat162_rn(v0, v1);
            __nv_bfloat162 p1 = __floats2bfloat162_rn(v2, v3);
            unsigned int* dst = dstbase + (((size_t)(bb*HH + h))*SS + s)*16 + (hd >> 1);
            dst[0] = reinterpret_cast<unsigned int&>(p0);
            dst[1] = reinterpret_cast<unsigned int&>(p1);
        }
    }
}

// ---------------------------------------------------------------------------
// bf16 dot helper: q (16 bf16x2 regs) . k-row from smem (stride 20 u32)
// ---------------------------------------------------------------------------
__device__ __forceinline__ float dot32(const __nv_bfloat162* qh,
                                       const unsigned int* Kc, int kloc)
{
    const uint4* kp = (const uint4*)&Kc[kloc*20];
    uint4 ka = kp[0], kb4 = kp[1], kc = kp[2], kd = kp[3];
    unsigned int kv[16] = {ka.x,ka.y,ka.z,ka.w, kb4.x,kb4.y,kb4.z,kb4.w,
                           kc.x,kc.y,kc.z,kc.w, kd.x,kd.y,kd.z,kd.w};
    const __nv_bfloat162* kh = (const __nv_bfloat162*)kv;
    __nv_bfloat162 a = __floats2bfloat162_rn(0.f, 0.f);
    #pragma unroll
    for (int i = 0; i < 16; i++) a = __hfma2(qh[i], kh[i], a);
    float2 f = __bfloat1622float2(a);
    return f.x + f.y;
}

// ---------------------------------------------------------------------------
// Kernel 4: fused attention: QK + softmax + mix + prob write + PV (tf32 mma).
// grid = (16 bh, 32 qtiles of 64 rows), 512 threads (16 warps).
// Pass A: causal Z per row (scores discarded). Pass B: recompute scores per
// 128-k chunk, p = e*ip + base -> prob (streaming store) + Ps(tf32) -> mma V.
// ---------------------------------------------------------------------------
#define QT 64
#define PS_STR 132
#define VS_STR 40
#define KC_STR 20
#define ATTN_SMEM ((QT*PS_STR + 128*VS_STR + 128*KC_STR + QT*KC_STR)*4)

__global__ __launch_bounds__(512, 2) void attn_fused_kernel(
    const float* __restrict__ l1p, const float* __restrict__ l2p,
    float* __restrict__ prob)
{
    extern __shared__ float sm[];
    float*        Psf = sm;                             // 64 x 132 (tf32 bits)
    unsigned int* Psu = (unsigned int*)Psf;
    float*        Vsf = sm + QT*PS_STR;                 // 128 x 40 (tf32 bits)
    unsigned int* Vsu = (unsigned int*)Vsf;
    unsigned int* Kc  = (unsigned int*)(sm + QT*PS_STR + 128*VS_STR); // 128 x 20
    unsigned int* Qs  = Kc + 128*KC_STR;                // 64 x 20

    const int tid = threadIdx.x;
    const int w = tid >> 5, lane = tid & 31;
    const int bh = blockIdx.x;
    const int q0 = (gridDim.y - 1 - blockIdx.y) * QT;   // heavy blocks first
    const int b  = bh >> 2;
    const float scale = 0.17677669529663687f;           // 1/sqrt(32)

    const int ktiles = (q0 + QT + 127) >> 7;            // causal chunk count

    // ---- load q rows (bf16x2) into smem ----
    if (tid < 256) {
        int row = tid >> 2, c4 = (tid & 3) * 4;
        uint4 v = *(const uint4*)(g_qb + ((size_t)bh*SS + q0 + row)*16 + c4);
        *(uint4*)&Qs[row*KC_STR + c4] = v;
    }
    __syncthreads();

    // ---------- Pass A: Z per row (causal chunks only) ----------
    float Z[4] = {0.f, 0.f, 0.f, 0.f};
    for (int t = 0; t < ktiles; t++) {
        __syncthreads();
        {
            int kr = tid >> 2, c4 = (tid & 3) * 4;
            uint4 v = *(const uint4*)(g_kb + ((size_t)bh*SS + t*128 + kr)*16 + c4);
            *(uint4*)&Kc[kr*KC_STR + c4] = v;
        }
        __syncthreads();
        #pragma unroll
        for (int r = 0; r < 4; r++) {
            const int qg = q0 + w*4 + r;
            const uint4* qp = (const uint4*)&Qs[(w*4 + r)*KC_STR];
            uint4 qa = qp[0], qb4 = qp[1], qc = qp[2], qd = qp[3];
            unsigned int qv[16] = {qa.x,qa.y,qa.z,qa.w, qb4.x,qb4.y,qb4.z,qb4.w,
                                   qc.x,qc.y,qc.z,qc.w, qd.x,qd.y,qd.z,qd.w};
            const __nv_bfloat162* qh = (const __nv_bfloat162*)qv;
            #pragma unroll
            for (int j = 0; j < 4; j++) {
                int kloc = j*32 + lane;
                int kg = t*128 + kloc;
                float s = dot32(qh, Kc, kloc) * scale;
                Z[r] += (kg > qg) ? 0.f : __expf(s);
            }
        }
    }
    #pragma unroll
    for (int r = 0; r < 4; r++) {
        #pragma unroll
        for (int o = 16; o; o >>= 1)
            Z[r] += __shfl_xor_sync(0xffffffffu, Z[r], o);
    }
    const float l1 = *l1p, l2 = *l2p;
    const float cp = (1.f - l1) * (1.f - l2);
    float ip[4];
    #pragma unroll
    for (int r = 0; r < 4; r++) ip[r] = cp / Z[r];

    // ---------- Pass B: recompute + prob write + PV mma ----------
    const int mg = w & 3, ng = w >> 2;
    const int g = lane >> 2, t4 = lane & 3;
    float acc[4] = {0.f, 0.f, 0.f, 0.f};
    const float* Vg = g_v + (size_t)bh*SS*HD;

    for (int c = 0; c < SS/128; c++) {
        const int causal = (c < ktiles);
        __syncthreads();   // previous mma reads done
        // load V chunk as tf32
        #pragma unroll
        for (int rep = 0; rep < 2; rep++) {
            int idx = tid + 512*rep;
            int vr = idx >> 3, vc = (idx & 7) * 4;
            float4 v = *(const float4*)(Vg + (size_t)(c*128 + vr)*HD + vc);
            uint4 cv = { f2tf32(v.x), f2tf32(v.y), f2tf32(v.z), f2tf32(v.w) };
            *(uint4*)&Vsu[vr*VS_STR + vc] = cv;
        }
        // load K chunk (causal only)
        if (causal) {
            int kr = tid >> 2, c4 = (tid & 3) * 4;
            uint4 v = *(const uint4*)(g_kb + ((size_t)bh*SS + c*128 + kr)*16 + c4);
            *(uint4*)&Kc[kr*KC_STR + c4] = v;
        }
        __syncthreads();

        // compute p for rows w*4..w*4+3, ks c*128 + j*32 + lane
        #pragma unroll
        for (int r = 0; r < 4; r++) {
            const int qg = q0 + w*4 + r;
            const float* brow = g_base + ((size_t)b*SS + qg)*SS;
            float* prow = prob + ((size_t)bh*SS + qg)*SS;
            if (causal) {
                const uint4* qp = (const uint4*)&Qs[(w*4 + r)*KC_STR];
                uint4 qa = qp[0], qb4 = qp[1], qc = qp[2], qd = qp[3];
                unsigned int qv[16] = {qa.x,qa.y,qa.z,qa.w, qb4.x,qb4.y,qb4.z,qb4.w,
                                       qc.x,qc.y,qc.z,qc.w, qd.x,qd.y,qd.z,qd.w};
                const __nv_bfloat162* qh = (const __nv_bfloat162*)qv;
                #pragma unroll
                for (int j = 0; j < 4; j++) {
                    int kloc = j*32 + lane;
                    int kg = c*128 + kloc;
                    float s = dot32(qh, Kc, kloc) * scale;
                    float e = (kg > qg) ? 0.f : __expf(s);
                    float p = fmaf(e, ip[r], __ldg(brow + kg));
                    __stcs(prow + kg, p);
                    Psu[(w*4 + r)*PS_STR + kloc] = f2tf32(p);
                }
            } else {
                #pragma unroll
                for (int j = 0; j < 4; j++) {
                    int kloc = j*32 + lane;
                    int kg = c*128 + kloc;
                    float p = __ldg(brow + kg);
                    __stcs(prow + kg, p);
                    Psu[(w*4 + r)*PS_STR + kloc] = f2tf32(p);
                }
            }
        }
        __syncthreads();

        // mma: m16n8k8 tf32, warp tile (mg, ng), k = 128
        #pragma unroll
        for (int kk = 0; kk < 128; kk += 8) {
            unsigned int a0 = Psu[(mg*16 + g)*PS_STR + kk + t4];
            unsigned int a1 = Psu[(mg*16 + g + 8)*PS_STR + kk + t4];
            unsigned int a2 = Psu[(mg*16 + g)*PS_STR + kk + t4 + 4];
            unsigned int a3 = Psu[(mg*16 + g + 8)*PS_STR + kk + t4 + 4];
            unsigned int b0 = Vsu[(kk + t4)*VS_STR + ng*8 + g];
            unsigned int b1 = Vsu[(kk + t4 + 4)*VS_STR + ng*8 + g];
            asm volatile(
                "mma.sync.aligned.m16n8k8.row.col.f32.tf32.tf32.f32 "
                "{%0,%1,%2,%3}, {%4,%5,%6,%7}, {%8,%9}, {%0,%1,%2,%3};"
                : "+f"(acc[0]), "+f"(acc[1]), "+f"(acc[2]), "+f"(acc[3])
                : "r"(a0), "r"(a1), "r"(a2), "r"(a3), "r"(b0), "r"(b1));
        }
    }

    // epilogue
    {
        const int orow = q0 + mg*16 + g;
        const int col = ng*8 + 2*t4;
        float2 lo = { acc[0], acc[1] };
        float2 hi = { acc[2], acc[3] };
        *(float2*)&g_o[((size_t)bh*SS + orow)*HD + col]     = lo;
        *(float2*)&g_o[((size_t)bh*SS + orow + 8)*HD + col] = hi;
    }
}

// ---------------------------------------------------------------------------
// Kernel 5: pred = out @ Wout + bout
// ---------------------------------------------------------------------------
__global__ void pred_kernel(const float* __restrict__ Wout,
                            const float* __restrict__ bout,
                            float* __restrict__ pred)
{
    int t = blockIdx.x;
    int d = threadIdx.x; // 0..127
    int bb = t >> 11, s = t & (SS-1);
    int h = d >> 5, hd = d & 31;
    float v = g_o[(((size_t)(bb*HH + h))*SS + s)*HD + hd] * Wout[d];
    __shared__ float red[4];
    #pragma unroll
    for (int o = 16; o; o >>= 1) v += __shfl_xor_sync(0xffffffffu, v, o);
    if ((d & 31) == 0) red[d >> 5] = v;
    __syncthreads();
    if (d == 0) pred[t] = red[0] + red[1] + red[2] + red[3] + bout[0];
}

// ---------------------------------------------------------------------------
extern "C" void kernel_launch(void* const* d_in, const int* in_sizes, int n_in,
                              void* d_out, int out_size)
{
    const int*   item_in   = (const int*)  d_in[0];
    const int*   skill_in  = (const int*)  d_in[1];
    const int*   label_in  = (const int*)  d_in[2];
    const int*   item_ids  = (const int*)  d_in[3];
    const int*   skill_ids = (const int*)  d_in[4];
    const float* rel       = (const float*)d_in[5];
    const float* ts        = (const float*)d_in[6];
    const float* item_emb  = (const float*)d_in[7];
    const float* skill_emb = (const float*)d_in[8];
    const float* Win       = (const float*)d_in[9];
    const float* b_in      = (const float*)d_in[10];
    const float* Wq        = (const float*)d_in[11];
    const float* bq        = (const float*)d_in[12];
    const float* Wk        = (const float*)d_in[13];
    const float* bk        = (const float*)d_in[14];
    const float* Wv        = (const float*)d_in[15];
    const float* bv        = (const float*)d_in[16];
    const float* Wout      = (const float*)d_in[17];
    const float* bout      = (const float*)d_in[18];
    const float* l1        = (const float*)d_in[19];
    const float* l2        = (const float*)d_in[20];

    float* pred = (float*)d_out;          // [B,S,1] = 8192
    float* prob = pred + NTOK;            // [B,H,S,S]

    cudaFuncSetAttribute(attn_fused_kernel,
                         cudaFuncAttributeMaxDynamicSharedMemorySize,
                         ATTN_SMEM);

    build_kernel<<<NTOK, 128>>>(item_in, skill_in, label_in, item_ids,
                                skill_ids, item_emb, skill_emb);

    base_kernel<<<NTOK, 256>>>(ts, rel, l1, l2);

    // H = relu(X @ Win + b_in)
    sgemm_kernel<<<dim3(4, 128, 1), 256>>>(Win, b_in, Win, b_in, Win, b_in,
                                           512, 256, 0);
    // q,k,v in one launch (z-dispatch)
    sgemm_kernel<<<dim3(2, 128, 3), 256>>>(Wq, bq, Wk, bk, Wv, bv,
                                           256, 128, 1);

    attn_fused_kernel<<<dim3(NBH, SS/QT), 512, ATTN_SMEM>>>(l1, l2, prob);

    pred_kernel<<<NTOK, 128>>>(Wout, bout, pred);
}